// round 8
// baseline (speedup 1.0000x reference)
#include <cuda_runtime.h>
#include <cuda_fp16.h>
#include <cstdint>
#include <cmath>

// scratch: mid tensor x [4,128,256,256] fp16, gated tensor [4,64,256,256] fp32
static __device__ __align__(16) __half g_xmid[(size_t)4 * 128 * 256 * 256];
static __device__ __align__(16) float  g_gate[(size_t)4 * 64 * 256 * 256];

// ---------------------------------------------------------------------------
// f32x2 packed helpers (Blackwell FFMA2 path — only reachable via PTX)
// ---------------------------------------------------------------------------
__device__ __forceinline__ unsigned long long pack2(float lo, float hi)
{
    unsigned long long r;
    asm("mov.b64 %0, {%1, %2};" : "=l"(r) : "f"(lo), "f"(hi));
    return r;
}
__device__ __forceinline__ void unpack2(unsigned long long v, float& lo, float& hi)
{
    asm("mov.b64 {%0, %1}, %2;" : "=f"(lo), "=f"(hi) : "l"(v));
}
__device__ __forceinline__ unsigned long long fma2(unsigned long long a,
                                                   unsigned long long b,
                                                   unsigned long long c)
{
    unsigned long long d;
    asm("fma.rn.f32x2 %0, %1, %2, %3;" : "=l"(d) : "l"(a), "l"(b), "l"(c));
    return d;
}

// ---------------------------------------------------------------------------
// 8-point complex FFT (single thread). s=+1 forward (e^{-i}), s=-1 inverse
// (e^{+i}), NO scaling.
// ---------------------------------------------------------------------------
__device__ __forceinline__ void cfft8(float zr[8], float zi[8], const float s)
{
    const float cc = 0.70710678118654752440f;
    float t0r = zr[0] + zr[4], t0i = zi[0] + zi[4];
    float t1r = zr[0] - zr[4], t1i = zi[0] - zi[4];
    float t2r = zr[2] + zr[6], t2i = zi[2] + zi[6];
    float t3r = zr[2] - zr[6], t3i = zi[2] - zi[6];
    float E0r = t0r + t2r, E0i = t0i + t2i;
    float E2r = t0r - t2r, E2i = t0i - t2i;
    float E1r = t1r + s * t3i, E1i = t1i - s * t3r;
    float E3r = t1r - s * t3i, E3i = t1i + s * t3r;
    float u0r = zr[1] + zr[5], u0i = zi[1] + zi[5];
    float u1r = zr[1] - zr[5], u1i = zi[1] - zi[5];
    float u2r = zr[3] + zr[7], u2i = zi[3] + zi[7];
    float u3r = zr[3] - zr[7], u3i = zi[3] - zi[7];
    float O0r = u0r + u2r, O0i = u0i + u2i;
    float O2r = u0r - u2r, O2i = u0i - u2i;
    float O1r = u1r + s * u3i, O1i = u1i - s * u3r;
    float O3r = u1r - s * u3i, O3i = u1i + s * u3r;
    float T0r = O0r, T0i = O0i;
    float T1r = cc * (O1r + s * O1i), T1i = cc * (O1i - s * O1r);
    float T2r = s * O2i,              T2i = -s * O2r;
    float T3r = cc * (s * O3i - O3r), T3i = -cc * (O3i + s * O3r);
    zr[0] = E0r + T0r; zi[0] = E0i + T0i;
    zr[4] = E0r - T0r; zi[4] = E0i - T0i;
    zr[1] = E1r + T1r; zi[1] = E1i + T1i;
    zr[5] = E1r - T1r; zi[5] = E1i - T1i;
    zr[2] = E2r + T2r; zi[2] = E2i + T2i;
    zr[6] = E2r - T2r; zi[6] = E2i - T2i;
    zr[3] = E3r + T3r; zi[3] = E3i + T3i;
    zr[7] = E3r - T3r; zi[7] = E3i - T3i;
}

// ---------------------------------------------------------------------------
// Kernel F3 (256 threads, 2 blocks/SM, fused): per patch (b, ph, pw):
//   phase 1: 1x1 conv GEMM 256 slots x 64 px (k=64), f32x2, acc in regs
//   phase 2: spill acc -> sMid (aliases dead sWT/sIn) + stage filter to smem,
//            then cooperative register FFT: 2 threads per channel,
//            row halves split, columns via one shfl.xor(16) DIF/DIT stage.
// smem: phase1 sWT[64][256] + sIn[2][64][64] = 24576 fl = 98,304 B
//       phase2 alias: sMid[256][68] (17408 fl) | sFilt[128][41] (5248 fl)
// ---------------------------------------------------------------------------
__global__ void __launch_bounds__(256, 2) kF3(const float* __restrict__ img,
                                              const float* __restrict__ evt,
                                              const float* __restrict__ w_img,
                                              const float* __restrict__ w_evt,
                                              const float* __restrict__ filt)
{
    extern __shared__ float sm[];
    float* sWT   = sm;            // [64][256]
    float* sIn   = sm + 16384;    // [2][64][64]
    float* sMid  = sm;            // [256][68] alias
    float* sFilt = sm + 17408;    // [128][41] alias (ends 22656 < 24576)

    const int tid = threadIdx.x;
    const int pw = blockIdx.x, ph = blockIdx.y, b = blockIdx.z;

    // weights transposed: sWT[k][slot] (slot<128: img oc, >=128: event oc)
    for (int i = tid; i < 64 * 128; i += 256) {
        int k = i >> 7, o = i & 127;
        sWT[k * 256 + o]       = w_img[o * 64 + k];
        sWT[k * 256 + 128 + o] = w_evt[o * 64 + k];
    }
    // patch pixels: 64 ch x 64 px
    {
        const float4* img4 = reinterpret_cast<const float4*>(img);
        const float4* evt4 = reinterpret_cast<const float4*>(evt);
        for (int i = tid; i < 64 * 16; i += 256) {
            int c = i >> 4, q = i & 15;
            int r = q >> 1, hh = q & 1;
            int g4 = (((b * 64 + c) * 256 + ph * 8 + r) * 256 + pw * 8) / 4 + hh;
            *reinterpret_cast<float4*>(&sIn[c * 64 + q * 4])        = img4[g4];
            *reinterpret_cast<float4*>(&sIn[4096 + c * 64 + q * 4]) = evt4[g4];
        }
    }
    __syncthreads();

    // GEMM: 256 slots x 64 px, k=64; thread tile 8 slots x 8 px (f32x2)
    unsigned long long acc[32];
#pragma unroll
    for (int i = 0; i < 32; i++) acc[i] = 0ULL;
    const int rb = tid >> 3, cb = tid & 7;
    const int r0 = rb * 8, c0 = cb * 8;
    {
        const float* pin = sIn + ((r0 >= 128) ? 4096 : 0);
#pragma unroll 4
        for (int k = 0; k < 64; k++) {
            float4 w0 = *reinterpret_cast<const float4*>(&sWT[k * 256 + r0]);
            float4 w1 = *reinterpret_cast<const float4*>(&sWT[k * 256 + r0 + 4]);
            ulonglong2 xa = *reinterpret_cast<const ulonglong2*>(&pin[k * 64 + c0]);
            ulonglong2 xb = *reinterpret_cast<const ulonglong2*>(&pin[k * 64 + c0 + 4]);
            unsigned long long xv[4] = {xa.x, xa.y, xb.x, xb.y};
            float wf[8] = {w0.x, w0.y, w0.z, w0.w, w1.x, w1.y, w1.z, w1.w};
#pragma unroll
            for (int i = 0; i < 8; i++) {
                unsigned long long wp = pack2(wf[i], wf[i]);
#pragma unroll
                for (int j = 0; j < 4; j++)
                    acc[i * 4 + j] = fma2(wp, xv[j], acc[i * 4 + j]);
            }
        }
    }
    __syncthreads();   // sWT/sIn dead -> region becomes sMid | sFilt

    // spill acc -> sMid [256][68]; concurrently stage filter -> sFilt
#pragma unroll
    for (int i = 0; i < 8; i++)
#pragma unroll
        for (int j = 0; j < 4; j++) {
            float lo, hi;
            unpack2(acc[i * 4 + j], lo, hi);
            *reinterpret_cast<float2*>(&sMid[(r0 + i) * 68 + c0 + 2 * j]) =
                make_float2(lo, hi);
        }
    for (int i = tid; i < 128 * 40; i += 256) {
        int o = i / 40, j = i - o * 40;
        sFilt[o * 41 + j] = filt[i];
    }
    __syncthreads();

    // ---- phase 2: cooperative FFT. warp w, lane l: h = l>>4 (row half),
    // o = w*16 + (l&15) (channel). 2 threads per channel.
    {
        const int lane = tid & 31;
        const int w    = tid >> 5;
        const int h    = lane >> 4;              // 0: rows 0-3, 1: rows 4-7
        const int o    = w * 16 + (lane & 15);
        const bool hB  = (h == 1);
        const float C7 = 0.70710678118654752440f;

        const float* rowI = sMid + o * 68;
        const float* rowE = sMid + (128 + o) * 68;

        float Zr[32], Zi[32];   // local 4 rows x 8 cols

        // stage A: row FFTs of z = img + i*event (rows h*4 .. h*4+3)
#pragma unroll
        for (int j = 0; j < 4; j++) {
            const int R = h * 4 + j;
            float zr[8], zi[8];
            float4 a0 = *reinterpret_cast<const float4*>(rowI + R * 8);
            float4 a1 = *reinterpret_cast<const float4*>(rowI + R * 8 + 4);
            float4 b0 = *reinterpret_cast<const float4*>(rowE + R * 8);
            float4 b1 = *reinterpret_cast<const float4*>(rowE + R * 8 + 4);
            zr[0]=a0.x; zr[1]=a0.y; zr[2]=a0.z; zr[3]=a0.w;
            zr[4]=a1.x; zr[5]=a1.y; zr[6]=a1.z; zr[7]=a1.w;
            zi[0]=b0.x; zi[1]=b0.y; zi[2]=b0.z; zi[3]=b0.w;
            zi[4]=b1.x; zi[5]=b1.y; zi[6]=b1.z; zi[7]=b1.w;
            cfft8(zr, zi, 1.0f);
#pragma unroll
            for (int c = 0; c < 8; c++) { Zr[j * 8 + c] = zr[c]; Zi[j * 8 + c] = zi[c]; }
        }

        // stage B-fwd: 8-pt column FFTs, DIF split across thread pair.
        // After: Z[k][c] = F_{2k+h}(column c).
#pragma unroll
        for (int c = 0; c < 8; c++) {
            float lr[4], li[4], rr[4], ri[4];
#pragma unroll
            for (int j = 0; j < 4; j++) { lr[j] = Zr[j * 8 + c]; li[j] = Zi[j * 8 + c]; }
#pragma unroll
            for (int j = 0; j < 4; j++) {
                rr[j] = __shfl_xor_sync(0xffffffffu, lr[j], 16);
                ri[j] = __shfl_xor_sync(0xffffffffu, li[j], 16);
            }
            float tr[4], ti[4];
            if (!hB) {   // a_j = z_j + z_{j+4}
#pragma unroll
                for (int j = 0; j < 4; j++) { tr[j] = lr[j] + rr[j]; ti[j] = li[j] + ri[j]; }
            } else {     // b_j = (z_j - z_{j+4}) * W8^j
                float dr[4], di[4];
#pragma unroll
                for (int j = 0; j < 4; j++) { dr[j] = rr[j] - lr[j]; di[j] = ri[j] - li[j]; }
                tr[0] = dr[0];               ti[0] = di[0];
                tr[1] = C7 * (dr[1] + di[1]); ti[1] = C7 * (di[1] - dr[1]);
                tr[2] = di[2];               ti[2] = -dr[2];
                tr[3] = C7 * (di[3] - dr[3]); ti[3] = -C7 * (dr[3] + di[3]);
            }
            // forward FFT4 (e^{-i})
            float s0r = tr[0] + tr[2], s0i = ti[0] + ti[2];
            float s1r = tr[0] - tr[2], s1i = ti[0] - ti[2];
            float s2r = tr[1] + tr[3], s2i = ti[1] + ti[3];
            float s3r = tr[1] - tr[3], s3i = ti[1] - ti[3];
            Zr[0 * 8 + c] = s0r + s2r; Zi[0 * 8 + c] = s0i + s2i;
            Zr[1 * 8 + c] = s1r + s3i; Zi[1 * 8 + c] = s1i - s3r;
            Zr[2 * 8 + c] = s0r - s2r; Zi[2 * 8 + c] = s0i - s2i;
            Zr[3 * 8 + c] = s1r - s3i; Zi[3 * 8 + c] = s1i + s3r;
        }

        // stage B-combine+inverse: pairs (v, m=(8-v)&7); partner bins are
        // thread-local because n=(8-u)&7 preserves parity.
        const float* fo = sFilt + o * 41;
        const int vv[5] = {0, 4, 1, 2, 3};
        const int mm[5] = {0, 4, 7, 6, 5};
#pragma unroll
        for (int pidx = 0; pidx < 5; pidx++) {
            const int v = vv[pidx], m = mm[pidx];
            float xr[4], xi[4];
#pragma unroll
            for (int k = 0; k < 4; k++) {
                const int u  = 2 * k + h;
                const int kn = hB ? (3 - k) : ((4 - k) & 3);
                float pr = Zr[k * 8 + v],  pi_ = Zi[k * 8 + v];
                float qr = Zr[kn * 8 + m], qi  = Zi[kn * 8 + m];
                float Ir = 0.5f * (pr + qr), Ii = 0.5f * (pi_ - qi);
                float f  = fo[u * 5 + v];
                float Er = 0.5f * f * (pi_ + qi), Ei = 0.5f * f * (qr - pr);
                float ar = Ir + 1.0f;
                xr[k] = ar * Er - Ii * Ei;
                xi[k] = ar * Ei + Ii * Er;
            }
            // IFFT4 (e^{+i}, unscaled)
            float s0r = xr[0] + xr[2], s0i = xi[0] + xi[2];
            float s1r = xr[0] - xr[2], s1i = xi[0] - xi[2];
            float s2r = xr[1] + xr[3], s2i = xi[1] + xi[3];
            float s3r = xr[1] - xr[3], s3i = xi[1] - xi[3];
            float gr[4], gi[4];
            gr[0] = s0r + s2r; gi[0] = s0i + s2i;
            gr[1] = s1r - s3i; gi[1] = s1i + s3r;
            gr[2] = s0r - s2r; gi[2] = s0i - s2i;
            gr[3] = s1r + s3i; gi[3] = s1i - s3r;
            float hr[4], hi[4];
#pragma unroll
            for (int j = 0; j < 4; j++) {
                hr[j] = __shfl_xor_sync(0xffffffffu, gr[j], 16);
                hi[j] = __shfl_xor_sync(0xffffffffu, gi[j], 16);
            }
            if (!hB) {   // z_j = G_j + W^{-j} H_j
                Zr[0*8+v] = gr[0] + hr[0];                 Zi[0*8+v] = gi[0] + hi[0];
                Zr[1*8+v] = gr[1] + C7 * (hr[1] - hi[1]);  Zi[1*8+v] = gi[1] + C7 * (hr[1] + hi[1]);
                Zr[2*8+v] = gr[2] - hi[2];                 Zi[2*8+v] = gi[2] + hr[2];
                Zr[3*8+v] = gr[3] - C7 * (hr[3] + hi[3]);  Zi[3*8+v] = gi[3] + C7 * (hr[3] - hi[3]);
            } else {     // z_{j+4} = H_j - W^{-j} G_j
                Zr[0*8+v] = hr[0] - gr[0];                 Zi[0*8+v] = hi[0] - gi[0];
                Zr[1*8+v] = hr[1] - C7 * (gr[1] - gi[1]);  Zi[1*8+v] = hi[1] - C7 * (gr[1] + gi[1]);
                Zr[2*8+v] = hr[2] + gi[2];                 Zi[2*8+v] = hi[2] - gr[2];
                Zr[3*8+v] = hr[3] + C7 * (gr[3] + gi[3]);  Zi[3*8+v] = hi[3] - C7 * (gr[3] - gi[3]);
            }
        }

        // stage C: row inverse (hermitian extension over v), 1/64, fp16 store
        __half* outp = g_xmid + (((size_t)(b * 128 + o) * 256 + ph * 8) * 256
                                 + pw * 8);
        const float sc = 1.0f / 64.0f;
#pragma unroll
        for (int j = 0; j < 4; j++) {
            const int R = h * 4 + j;
            float zr[8], zi[8];
#pragma unroll
            for (int v = 0; v < 5; v++) { zr[v] = Zr[j * 8 + v]; zi[v] = Zi[j * 8 + v]; }
            zr[5] = Zr[j * 8 + 3]; zi[5] = -Zi[j * 8 + 3];
            zr[6] = Zr[j * 8 + 2]; zi[6] = -Zi[j * 8 + 2];
            zr[7] = Zr[j * 8 + 1]; zi[7] = -Zi[j * 8 + 1];
            cfft8(zr, zi, -1.0f);
            __half2 hh[4];
#pragma unroll
            for (int t = 0; t < 4; t++)
                hh[t] = __floats2half2_rn(zr[2 * t] * sc, zr[2 * t + 1] * sc);
            *reinterpret_cast<uint4*>(outp + (size_t)R * 256) =
                *reinterpret_cast<uint4*>(hh);
        }
    }
}

// ---------------------------------------------------------------------------
// Kernel DW: depthwise 3x3 (SAME) on channel pair (c, c+64), exact GELU gate.
// Block = 64x16 pixel tile of one (b, c). Reads fp16 xmid.
// ---------------------------------------------------------------------------
__global__ void __launch_bounds__(256) kDW(const float* __restrict__ w_dw)
{
    __shared__ float sH[2 * 18 * 68];

    const int tid = threadIdx.x;
    const int b = blockIdx.z >> 6, c = blockIdx.z & 63;
    const int x0 = blockIdx.x * 64, y0 = blockIdx.y * 16;

    float w1[9], w2[9];
#pragma unroll
    for (int j = 0; j < 9; j++) {
        w1[j] = w_dw[c * 9 + j];
        w2[j] = w_dw[(c + 64) * 9 + j];
    }

    const __half* src0 = g_xmid + (size_t)(b * 128 + c) * 65536;
    const __half* src1 = src0 + (size_t)64 * 65536;

    for (int i = tid; i < 18 * 66; i += 256) {
        int y = i / 66, x = i - y * 66;
        int gy = y0 + y - 1, gx = x0 + x - 1;
        float v0 = 0.f, v1 = 0.f;
        if (gy >= 0 && gy < 256 && gx >= 0 && gx < 256) {
            size_t gi = (size_t)gy * 256 + gx;
            v0 = __half2float(src0[gi]);
            v1 = __half2float(src1[gi]);
        }
        sH[y * 68 + x]        = v0;
        sH[1224 + y * 68 + x] = v1;
    }
    __syncthreads();

    const int px = tid & 63, ty = tid >> 6;
    float* dst = g_gate + (size_t)(b * 64 + c) * 65536;
#pragma unroll
    for (int yy = 0; yy < 4; yy++) {
        int py = ty * 4 + yy;
        float a = 0.f, bb = 0.f;
#pragma unroll
        for (int dy = 0; dy < 3; dy++)
#pragma unroll
            for (int dx = 0; dx < 3; dx++) {
                a  = fmaf(sH[(py + dy) * 68 + px + dx],        w1[dy * 3 + dx], a);
                bb = fmaf(sH[1224 + (py + dy) * 68 + px + dx], w2[dy * 3 + dx], bb);
            }
        float gl = 0.5f * a * (1.0f + erff(a * 0.70710678118654752f));
        dst[(size_t)(y0 + py) * 256 + x0 + px] = gl * bb;
    }
}

// ---------------------------------------------------------------------------
// Kernel Out: 1x1 projection. Block = one image row (256 px), all 64 k.
// GEMM 64oc x 256px x 64k, thread tile 8x8, f32x2 FMAs. float4 gate loads.
// ---------------------------------------------------------------------------
__global__ void __launch_bounds__(256, 2) kOut(const float* __restrict__ w_out,
                                               float* __restrict__ out)
{
    extern __shared__ float sm[];
    float* sG   = sm;          // [64][256]
    float* sWoT = sm + 16384;  // [64][64]

    const int tid = threadIdx.x;
    const int y = blockIdx.x, b = blockIdx.y;

    for (int i = tid; i < 64 * 64; i += 256) {
        int k = i >> 6, o = i & 63;
        sWoT[k * 64 + o] = w_out[o * 64 + k];
    }
    {
        const float4* gate4 = reinterpret_cast<const float4*>(g_gate);
        for (int i = tid; i < 64 * 64; i += 256) {
            int k = i >> 6, p4 = i & 63;
            *reinterpret_cast<float4*>(&sG[k * 256 + p4 * 4]) =
                gate4[((size_t)(b * 64 + k) * 65536 + (size_t)y * 256) / 4 + p4];
        }
    }
    __syncthreads();

    const int ob = tid >> 5, pb = tid & 31;
    const int oc0 = ob * 8, p0 = pb * 8;
    unsigned long long acc[32];
#pragma unroll
    for (int i = 0; i < 32; i++) acc[i] = 0ULL;
#pragma unroll 8
    for (int k = 0; k < 64; k++) {
        float4 w0 = *reinterpret_cast<const float4*>(&sWoT[k * 64 + oc0]);
        float4 w1 = *reinterpret_cast<const float4*>(&sWoT[k * 64 + oc0 + 4]);
        ulonglong2 ga = *reinterpret_cast<const ulonglong2*>(&sG[k * 256 + p0]);
        ulonglong2 gb = *reinterpret_cast<const ulonglong2*>(&sG[k * 256 + p0 + 4]);
        unsigned long long gv[4] = {ga.x, ga.y, gb.x, gb.y};
        float wf[8] = {w0.x, w0.y, w0.z, w0.w, w1.x, w1.y, w1.z, w1.w};
#pragma unroll
        for (int i = 0; i < 8; i++) {
            unsigned long long wp = pack2(wf[i], wf[i]);
#pragma unroll
            for (int j = 0; j < 4; j++)
                acc[i * 4 + j] = fma2(wp, gv[j], acc[i * 4 + j]);
        }
    }
#pragma unroll
    for (int i = 0; i < 8; i++) {
        float v[8];
#pragma unroll
        for (int j = 0; j < 4; j++) unpack2(acc[i * 4 + j], v[2 * j], v[2 * j + 1]);
        size_t ga = ((size_t)(b * 64 + oc0 + i) * 256 + y) * 256 + p0;
        float4 q0 = {v[0], v[1], v[2], v[3]};
        float4 q1 = {v[4], v[5], v[6], v[7]};
        *reinterpret_cast<float4*>(&out[ga])     = q0;
        *reinterpret_cast<float4*>(&out[ga + 4]) = q1;
    }
}

// ---------------------------------------------------------------------------
extern "C" void kernel_launch(void* const* d_in, const int* in_sizes, int n_in,
                              void* d_out, int out_size)
{
    const float* img   = (const float*)d_in[0];
    const float* evt   = (const float*)d_in[1];
    const float* w_img = (const float*)d_in[2];
    const float* w_evt = (const float*)d_in[3];
    const float* w_dw  = (const float*)d_in[4];
    const float* filt  = (const float*)d_in[5];
    const float* w_out = (const float*)d_in[6];
    float* out = (float*)d_out;

    const int smemF = 24576 * 4;   // 98,304 B -> 2 blocks/SM
    const int smemO = 20480 * 4;   // 81,920 B -> 2 blocks/SM
    cudaFuncSetAttribute(kF3,  cudaFuncAttributeMaxDynamicSharedMemorySize, smemF);
    cudaFuncSetAttribute(kOut, cudaFuncAttributeMaxDynamicSharedMemorySize, smemO);

    kF3<<<dim3(32, 32, 4), 256, smemF>>>(img, evt, w_img, w_evt, filt);
    kDW<<<dim3(4, 16, 256), 256>>>(w_dw);
    kOut<<<dim3(256, 4), 256, smemO>>>(w_out, out);
}

// round 9
// speedup vs baseline: 1.3151x; 1.3151x over previous
#include <cuda_runtime.h>
#include <cuda_fp16.h>
#include <cstdint>
#include <cmath>

// scratch: mid tensor x [4,128,256,256] fp16, gated tensor [4,64,256,256] fp16
static __device__ __align__(16) __half g_xmid[(size_t)4 * 128 * 256 * 256];
static __device__ __align__(16) __half g_gate[(size_t)4 * 64 * 256 * 256];

// ---------------------------------------------------------------------------
// f32x2 packed helpers
// ---------------------------------------------------------------------------
__device__ __forceinline__ unsigned long long pack2(float lo, float hi)
{
    unsigned long long r;
    asm("mov.b64 %0, {%1, %2};" : "=l"(r) : "f"(lo), "f"(hi));
    return r;
}
__device__ __forceinline__ void unpack2(unsigned long long v, float& lo, float& hi)
{
    asm("mov.b64 {%0, %1}, %2;" : "=f"(lo), "=f"(hi) : "l"(v));
}
__device__ __forceinline__ unsigned long long fma2(unsigned long long a,
                                                   unsigned long long b,
                                                   unsigned long long c)
{
    unsigned long long d;
    asm("fma.rn.f32x2 %0, %1, %2, %3;" : "=l"(d) : "l"(a), "l"(b), "l"(c));
    return d;
}

// ---------------------------------------------------------------------------
// 8-point complex FFT (single thread). s=+1 forward, s=-1 inverse, NO scaling.
// ---------------------------------------------------------------------------
__device__ __forceinline__ void cfft8(float zr[8], float zi[8], const float s)
{
    const float cc = 0.70710678118654752440f;
    float t0r = zr[0] + zr[4], t0i = zi[0] + zi[4];
    float t1r = zr[0] - zr[4], t1i = zi[0] - zi[4];
    float t2r = zr[2] + zr[6], t2i = zi[2] + zi[6];
    float t3r = zr[2] - zr[6], t3i = zi[2] - zi[6];
    float E0r = t0r + t2r, E0i = t0i + t2i;
    float E2r = t0r - t2r, E2i = t0i - t2i;
    float E1r = t1r + s * t3i, E1i = t1i - s * t3r;
    float E3r = t1r - s * t3i, E3i = t1i + s * t3r;
    float u0r = zr[1] + zr[5], u0i = zi[1] + zi[5];
    float u1r = zr[1] - zr[5], u1i = zi[1] - zi[5];
    float u2r = zr[3] + zr[7], u2i = zi[3] + zi[7];
    float u3r = zr[3] - zr[7], u3i = zi[3] - zi[7];
    float O0r = u0r + u2r, O0i = u0i + u2i;
    float O2r = u0r - u2r, O2i = u0i - u2i;
    float O1r = u1r + s * u3i, O1i = u1i - s * u3r;
    float O3r = u1r - s * u3i, O3i = u1i + s * u3r;
    float T0r = O0r, T0i = O0i;
    float T1r = cc * (O1r + s * O1i), T1i = cc * (O1i - s * O1r);
    float T2r = s * O2i,              T2i = -s * O2r;
    float T3r = cc * (s * O3i - O3r), T3i = -cc * (O3i + s * O3r);
    zr[0] = E0r + T0r; zi[0] = E0i + T0i;
    zr[4] = E0r - T0r; zi[4] = E0i - T0i;
    zr[1] = E1r + T1r; zi[1] = E1i + T1i;
    zr[5] = E1r - T1r; zi[5] = E1i - T1i;
    zr[2] = E2r + T2r; zi[2] = E2i + T2i;
    zr[6] = E2r - T2r; zi[6] = E2i - T2i;
    zr[3] = E3r + T3r; zi[3] = E3i + T3i;
    zr[7] = E3r - T3r; zi[7] = E3i - T3i;
}

// ---------------------------------------------------------------------------
// Kernel F4 (512 threads, 1 block/SM, 4 patch-pairs per block):
//   prologue: stage weights + filter + pixels(iter0); then per iter:
//     GEMM (overlaps previous iter's FFT across warps) -> sync_a ->
//     spill acc->sMid(fp16) + load pixels(it+1)->sIn -> sync_b ->
//     cooperative register FFT -> store fp16 x.
// smem (floats): sWT[64][256]=16384 | sFilt[128][41]=5248 |
//                sIn[2][64][128]=16384 | sMid(half)[256][136]=17408fl
// total 55424 fl = 221,696 B
// ---------------------------------------------------------------------------
__global__ void __launch_bounds__(512, 1) kF4(const float* __restrict__ img,
                                              const float* __restrict__ evt,
                                              const float* __restrict__ w_img,
                                              const float* __restrict__ w_evt,
                                              const float* __restrict__ filt)
{
    extern __shared__ float sm[];
    float*  sWT   = sm;                                    // [64][256]
    float*  sFilt = sm + 16384;                            // [128][41]
    float*  sIn   = sm + 21632;                            // [2][64][128]
    __half* sMidH = reinterpret_cast<__half*>(sm + 38016); // [256][136]

    const int tid = threadIdx.x;
    const int qx = blockIdx.x, ph = blockIdx.y, b = blockIdx.z;

    const float4* img4 = reinterpret_cast<const float4*>(img);
    const float4* evt4 = reinterpret_cast<const float4*>(evt);

    // prologue: weights (transposed), filter, pixels for iter 0
    for (int i = tid; i < 64 * 128; i += 512) {
        int k = i >> 7, o = i & 127;
        sWT[k * 256 + o]       = w_img[o * 64 + k];
        sWT[k * 256 + 128 + o] = w_evt[o * 64 + k];
    }
    for (int i = tid; i < 128 * 40; i += 512) {
        int o = i / 40, j = i - o * 40;
        sFilt[o * 41 + j] = filt[i];
    }
    {
        const int pw16 = qx * 4;
        for (int i = tid; i < 64 * 32; i += 512) {
            int c = i >> 5, q4 = i & 31;
            int r = q4 >> 2, xx = q4 & 3;
            int g4 = (((b * 64 + c) * 256 + ph * 8 + r) * 256 + pw16 * 16) / 4 + xx;
            *reinterpret_cast<float4*>(&sIn[c * 128 + q4 * 4])        = img4[g4];
            *reinterpret_cast<float4*>(&sIn[8192 + c * 128 + q4 * 4]) = evt4[g4];
        }
    }
    __syncthreads();

    // GEMM thread tile: 8 slots x 8 px
    const int rb = tid >> 4, cb = tid & 15;
    const int r0 = rb * 8, c0 = cb * 8;
    const float* pin = sIn + ((r0 >= 128) ? 8192 : 0);

    // FFT role: 2 threads per (channel, patch)
    const int lane = tid & 31;
    const int w    = tid >> 5;
    const int h    = lane >> 4;
    const int item = w * 16 + (lane & 15);
    const int o    = item & 127;
    const int pp   = item >> 7;
    const bool hB  = (h == 1);
    const float C7 = 0.70710678118654752440f;
    const __half* rowI = sMidH + o * 136 + pp * 8;
    const __half* rowE = sMidH + (128 + o) * 136 + pp * 8;
    const float* fo = sFilt + o * 41;

    for (int it = 0; it < 4; it++) {
        const int pw16 = qx * 4 + it;

        // ---- GEMM: 256 slots x 128 px, k=64 (f32x2) ----
        unsigned long long acc[32];
#pragma unroll
        for (int i = 0; i < 32; i++) acc[i] = 0ULL;
#pragma unroll 4
        for (int k = 0; k < 64; k++) {
            float4 w0 = *reinterpret_cast<const float4*>(&sWT[k * 256 + r0]);
            float4 w1 = *reinterpret_cast<const float4*>(&sWT[k * 256 + r0 + 4]);
            ulonglong2 xa = *reinterpret_cast<const ulonglong2*>(&pin[k * 128 + c0]);
            ulonglong2 xb = *reinterpret_cast<const ulonglong2*>(&pin[k * 128 + c0 + 4]);
            unsigned long long xv[4] = {xa.x, xa.y, xb.x, xb.y};
            float wf[8] = {w0.x, w0.y, w0.z, w0.w, w1.x, w1.y, w1.z, w1.w};
#pragma unroll
            for (int i = 0; i < 8; i++) {
                unsigned long long wp = pack2(wf[i], wf[i]);
#pragma unroll
                for (int j = 0; j < 4; j++)
                    acc[i * 4 + j] = fma2(wp, xv[j], acc[i * 4 + j]);
            }
        }
        __syncthreads();   // sync_a: sIn reads done; prev FFT done with sMid

        // ---- spill acc -> sMid fp16 ----
#pragma unroll
        for (int i = 0; i < 8; i++) {
            __half2 hh[4];
#pragma unroll
            for (int j = 0; j < 4; j++) {
                float lo, hi;
                unpack2(acc[i * 4 + j], lo, hi);
                hh[j] = __floats2half2_rn(lo, hi);
            }
            *reinterpret_cast<uint4*>(&sMidH[(r0 + i) * 136 + c0]) =
                *reinterpret_cast<uint4*>(hh);
        }
        // ---- load pixels for next iter into sIn ----
        if (it < 3) {
            const int pwn = pw16 + 1;
            for (int i = tid; i < 64 * 32; i += 512) {
                int c = i >> 5, q4 = i & 31;
                int r = q4 >> 2, xx = q4 & 3;
                int g4 = (((b * 64 + c) * 256 + ph * 8 + r) * 256 + pwn * 16) / 4 + xx;
                *reinterpret_cast<float4*>(&sIn[c * 128 + q4 * 4])        = img4[g4];
                *reinterpret_cast<float4*>(&sIn[8192 + c * 128 + q4 * 4]) = evt4[g4];
            }
        }
        __syncthreads();   // sync_b: sMid + sIn(next) ready

        // ---- cooperative register FFT ----
        float Zr[32], Zi[32];

        // stage A: row FFTs of z = img + i*event (rows h*4 .. h*4+3)
#pragma unroll
        for (int j = 0; j < 4; j++) {
            const int R = h * 4 + j;
            uint4 ra = *reinterpret_cast<const uint4*>(rowI + R * 16);
            uint4 rb2 = *reinterpret_cast<const uint4*>(rowE + R * 16);
            const __half2* ha = reinterpret_cast<const __half2*>(&ra);
            const __half2* hb = reinterpret_cast<const __half2*>(&rb2);
            float zr[8], zi[8];
#pragma unroll
            for (int t = 0; t < 4; t++) {
                float2 fa = __half22float2(ha[t]);
                float2 fb = __half22float2(hb[t]);
                zr[2 * t] = fa.x; zr[2 * t + 1] = fa.y;
                zi[2 * t] = fb.x; zi[2 * t + 1] = fb.y;
            }
            cfft8(zr, zi, 1.0f);
#pragma unroll
            for (int c = 0; c < 8; c++) { Zr[j * 8 + c] = zr[c]; Zi[j * 8 + c] = zi[c]; }
        }

        // stage B-fwd: 8-pt column FFTs, DIF split across thread pair
#pragma unroll
        for (int c = 0; c < 8; c++) {
            float lr[4], li[4], rr[4], ri[4];
#pragma unroll
            for (int j = 0; j < 4; j++) { lr[j] = Zr[j * 8 + c]; li[j] = Zi[j * 8 + c]; }
#pragma unroll
            for (int j = 0; j < 4; j++) {
                rr[j] = __shfl_xor_sync(0xffffffffu, lr[j], 16);
                ri[j] = __shfl_xor_sync(0xffffffffu, li[j], 16);
            }
            float tr[4], ti[4];
            if (!hB) {
#pragma unroll
                for (int j = 0; j < 4; j++) { tr[j] = lr[j] + rr[j]; ti[j] = li[j] + ri[j]; }
            } else {
                float dr[4], di[4];
#pragma unroll
                for (int j = 0; j < 4; j++) { dr[j] = rr[j] - lr[j]; di[j] = ri[j] - li[j]; }
                tr[0] = dr[0];               ti[0] = di[0];
                tr[1] = C7 * (dr[1] + di[1]); ti[1] = C7 * (di[1] - dr[1]);
                tr[2] = di[2];               ti[2] = -dr[2];
                tr[3] = C7 * (di[3] - dr[3]); ti[3] = -C7 * (dr[3] + di[3]);
            }
            float s0r = tr[0] + tr[2], s0i = ti[0] + ti[2];
            float s1r = tr[0] - tr[2], s1i = ti[0] - ti[2];
            float s2r = tr[1] + tr[3], s2i = ti[1] + ti[3];
            float s3r = tr[1] - tr[3], s3i = ti[1] - ti[3];
            Zr[0 * 8 + c] = s0r + s2r; Zi[0 * 8 + c] = s0i + s2i;
            Zr[1 * 8 + c] = s1r + s3i; Zi[1 * 8 + c] = s1i - s3r;
            Zr[2 * 8 + c] = s0r - s2r; Zi[2 * 8 + c] = s0i - s2i;
            Zr[3 * 8 + c] = s1r - s3i; Zi[3 * 8 + c] = s1i + s3r;
        }

        // stage B-combine+inverse
        const int vv[5] = {0, 4, 1, 2, 3};
        const int mm[5] = {0, 4, 7, 6, 5};
#pragma unroll
        for (int pidx = 0; pidx < 5; pidx++) {
            const int v = vv[pidx], m = mm[pidx];
            float xr[4], xi[4];
#pragma unroll
            for (int k = 0; k < 4; k++) {
                const int u  = 2 * k + h;
                const int kn = hB ? (3 - k) : ((4 - k) & 3);
                float pr = Zr[k * 8 + v],  pi_ = Zi[k * 8 + v];
                float qr = Zr[kn * 8 + m], qi  = Zi[kn * 8 + m];
                float Ir = 0.5f * (pr + qr), Ii = 0.5f * (pi_ - qi);
                float f  = fo[u * 5 + v];
                float Er = 0.5f * f * (pi_ + qi), Ei = 0.5f * f * (qr - pr);
                float ar = Ir + 1.0f;
                xr[k] = ar * Er - Ii * Ei;
                xi[k] = ar * Ei + Ii * Er;
            }
            float s0r = xr[0] + xr[2], s0i = xi[0] + xi[2];
            float s1r = xr[0] - xr[2], s1i = xi[0] - xi[2];
            float s2r = xr[1] + xr[3], s2i = xi[1] + xi[3];
            float s3r = xr[1] - xr[3], s3i = xi[1] - xi[3];
            float gr[4], gi[4];
            gr[0] = s0r + s2r; gi[0] = s0i + s2i;
            gr[1] = s1r - s3i; gi[1] = s1i + s3r;
            gr[2] = s0r - s2r; gi[2] = s0i - s2i;
            gr[3] = s1r + s3i; gi[3] = s1i - s3r;
            float hr[4], hi[4];
#pragma unroll
            for (int j = 0; j < 4; j++) {
                hr[j] = __shfl_xor_sync(0xffffffffu, gr[j], 16);
                hi[j] = __shfl_xor_sync(0xffffffffu, gi[j], 16);
            }
            if (!hB) {
                Zr[0*8+v] = gr[0] + hr[0];                 Zi[0*8+v] = gi[0] + hi[0];
                Zr[1*8+v] = gr[1] + C7 * (hr[1] - hi[1]);  Zi[1*8+v] = gi[1] + C7 * (hr[1] + hi[1]);
                Zr[2*8+v] = gr[2] - hi[2];                 Zi[2*8+v] = gi[2] + hr[2];
                Zr[3*8+v] = gr[3] - C7 * (hr[3] + hi[3]);  Zi[3*8+v] = gi[3] + C7 * (hr[3] - hi[3]);
            } else {
                Zr[0*8+v] = hr[0] - gr[0];                 Zi[0*8+v] = hi[0] - gi[0];
                Zr[1*8+v] = hr[1] - C7 * (gr[1] - gi[1]);  Zi[1*8+v] = hi[1] - C7 * (gr[1] + gi[1]);
                Zr[2*8+v] = hr[2] + gi[2];                 Zi[2*8+v] = hi[2] - gr[2];
                Zr[3*8+v] = hr[3] + C7 * (gr[3] + gi[3]);  Zi[3*8+v] = hi[3] - C7 * (gr[3] - gi[3]);
            }
        }

        // stage C: row inverse + fp16 store
        __half* outp = g_xmid + (((size_t)(b * 128 + o) * 256 + ph * 8) * 256
                                 + pw16 * 16 + pp * 8);
        const float sc = 1.0f / 64.0f;
#pragma unroll
        for (int j = 0; j < 4; j++) {
            const int R = h * 4 + j;
            float zr[8], zi[8];
#pragma unroll
            for (int v = 0; v < 5; v++) { zr[v] = Zr[j * 8 + v]; zi[v] = Zi[j * 8 + v]; }
            zr[5] = Zr[j * 8 + 3]; zi[5] = -Zi[j * 8 + 3];
            zr[6] = Zr[j * 8 + 2]; zi[6] = -Zi[j * 8 + 2];
            zr[7] = Zr[j * 8 + 1]; zi[7] = -Zi[j * 8 + 1];
            cfft8(zr, zi, -1.0f);
            __half2 hh[4];
#pragma unroll
            for (int t = 0; t < 4; t++)
                hh[t] = __floats2half2_rn(zr[2 * t] * sc, zr[2 * t + 1] * sc);
            *reinterpret_cast<uint4*>(outp + (size_t)R * 256) =
                *reinterpret_cast<uint4*>(hh);
        }
        // loop: GEMM(it+1) overlaps stragglers' FFT(it) until sync_a
    }
}

// ---------------------------------------------------------------------------
// Kernel DW: depthwise 3x3 (SAME) on channel pair (c, c+64), exact GELU gate.
// Reads fp16 xmid, writes fp16 gate.
// ---------------------------------------------------------------------------
__global__ void __launch_bounds__(256) kDW(const float* __restrict__ w_dw)
{
    __shared__ float sH[2 * 18 * 68];

    const int tid = threadIdx.x;
    const int b = blockIdx.z >> 6, c = blockIdx.z & 63;
    const int x0 = blockIdx.x * 64, y0 = blockIdx.y * 16;

    float w1[9], w2[9];
#pragma unroll
    for (int j = 0; j < 9; j++) {
        w1[j] = w_dw[c * 9 + j];
        w2[j] = w_dw[(c + 64) * 9 + j];
    }

    const __half* src0 = g_xmid + (size_t)(b * 128 + c) * 65536;
    const __half* src1 = src0 + (size_t)64 * 65536;

    for (int i = tid; i < 18 * 66; i += 256) {
        int y = i / 66, x = i - y * 66;
        int gy = y0 + y - 1, gx = x0 + x - 1;
        float v0 = 0.f, v1 = 0.f;
        if (gy >= 0 && gy < 256 && gx >= 0 && gx < 256) {
            size_t gi = (size_t)gy * 256 + gx;
            v0 = __half2float(src0[gi]);
            v1 = __half2float(src1[gi]);
        }
        sH[y * 68 + x]        = v0;
        sH[1224 + y * 68 + x] = v1;
    }
    __syncthreads();

    const int px = tid & 63, ty = tid >> 6;
    __half* dst = g_gate + (size_t)(b * 64 + c) * 65536;
#pragma unroll
    for (int yy = 0; yy < 4; yy++) {
        int py = ty * 4 + yy;
        float a = 0.f, bb = 0.f;
#pragma unroll
        for (int dy = 0; dy < 3; dy++)
#pragma unroll
            for (int dx = 0; dx < 3; dx++) {
                a  = fmaf(sH[(py + dy) * 68 + px + dx],        w1[dy * 3 + dx], a);
                bb = fmaf(sH[1224 + (py + dy) * 68 + px + dx], w2[dy * 3 + dx], bb);
            }
        float gl = 0.5f * a * (1.0f + erff(a * 0.70710678118654752f));
        dst[(size_t)(y0 + py) * 256 + x0 + px] = __float2half_rn(gl * bb);
    }
}

// ---------------------------------------------------------------------------
// Kernel Out: 1x1 projection. Block = one image row (256 px), all 64 k.
// GEMM 64oc x 256px x 64k, 8x8 f32x2 tiles; gate loaded fp16 -> fp32 smem.
// ---------------------------------------------------------------------------
__global__ void __launch_bounds__(256, 2) kOut(const float* __restrict__ w_out,
                                               float* __restrict__ out)
{
    extern __shared__ float sm[];
    float* sG   = sm;          // [64][256]
    float* sWoT = sm + 16384;  // [64][64]

    const int tid = threadIdx.x;
    const int y = blockIdx.x, b = blockIdx.y;

    for (int i = tid; i < 64 * 64; i += 256) {
        int k = i >> 6, o = i & 63;
        sWoT[k * 64 + o] = w_out[o * 64 + k];
    }
    for (int i = tid; i < 2048; i += 256) {   // 64 rows x 32 uint4 (8 halves)
        int k = i >> 5, p8 = i & 31;
        uint4 rh = *reinterpret_cast<const uint4*>(
            g_gate + (size_t)(b * 64 + k) * 65536 + (size_t)y * 256 + p8 * 8);
        const __half2* hp = reinterpret_cast<const __half2*>(&rh);
        float v[8];
#pragma unroll
        for (int t = 0; t < 4; t++) {
            float2 f2 = __half22float2(hp[t]);
            v[2 * t] = f2.x; v[2 * t + 1] = f2.y;
        }
        float4 q0 = {v[0], v[1], v[2], v[3]};
        float4 q1 = {v[4], v[5], v[6], v[7]};
        *reinterpret_cast<float4*>(&sG[k * 256 + p8 * 8])     = q0;
        *reinterpret_cast<float4*>(&sG[k * 256 + p8 * 8 + 4]) = q1;
    }
    __syncthreads();

    const int ob = tid >> 5, pb = tid & 31;
    const int oc0 = ob * 8, p0 = pb * 8;
    unsigned long long acc[32];
#pragma unroll
    for (int i = 0; i < 32; i++) acc[i] = 0ULL;
#pragma unroll 8
    for (int k = 0; k < 64; k++) {
        float4 w0 = *reinterpret_cast<const float4*>(&sWoT[k * 64 + oc0]);
        float4 w1 = *reinterpret_cast<const float4*>(&sWoT[k * 64 + oc0 + 4]);
        ulonglong2 ga = *reinterpret_cast<const ulonglong2*>(&sG[k * 256 + p0]);
        ulonglong2 gb = *reinterpret_cast<const ulonglong2*>(&sG[k * 256 + p0 + 4]);
        unsigned long long gv[4] = {ga.x, ga.y, gb.x, gb.y};
        float wf[8] = {w0.x, w0.y, w0.z, w0.w, w1.x, w1.y, w1.z, w1.w};
#pragma unroll
        for (int i = 0; i < 8; i++) {
            unsigned long long wp = pack2(wf[i], wf[i]);
#pragma unroll
            for (int j = 0; j < 4; j++)
                acc[i * 4 + j] = fma2(wp, gv[j], acc[i * 4 + j]);
        }
    }
#pragma unroll
    for (int i = 0; i < 8; i++) {
        float v[8];
#pragma unroll
        for (int j = 0; j < 4; j++) unpack2(acc[i * 4 + j], v[2 * j], v[2 * j + 1]);
        size_t ga = ((size_t)(b * 64 + oc0 + i) * 256 + y) * 256 + p0;
        float4 q0 = {v[0], v[1], v[2], v[3]};
        float4 q1 = {v[4], v[5], v[6], v[7]};
        *reinterpret_cast<float4*>(&out[ga])     = q0;
        *reinterpret_cast<float4*>(&out[ga + 4]) = q1;
    }
}

// ---------------------------------------------------------------------------
extern "C" void kernel_launch(void* const* d_in, const int* in_sizes, int n_in,
                              void* d_out, int out_size)
{
    const float* img   = (const float*)d_in[0];
    const float* evt   = (const float*)d_in[1];
    const float* w_img = (const float*)d_in[2];
    const float* w_evt = (const float*)d_in[3];
    const float* w_dw  = (const float*)d_in[4];
    const float* filt  = (const float*)d_in[5];
    const float* w_out = (const float*)d_in[6];
    float* out = (float*)d_out;

    const int smemF = 55424 * 4;   // 221,696 B -> 1 block/SM
    const int smemO = 20480 * 4;   //  81,920 B -> 2 blocks/SM
    cudaFuncSetAttribute(kF4,  cudaFuncAttributeMaxDynamicSharedMemorySize, smemF);
    cudaFuncSetAttribute(kOut, cudaFuncAttributeMaxDynamicSharedMemorySize, smemO);

    kF4<<<dim3(4, 32, 4), 512, smemF>>>(img, evt, w_img, w_evt, filt);
    kDW<<<dim3(4, 16, 256), 256>>>(w_dw);
    kOut<<<dim3(256, 4), 256, smemO>>>(w_out, out);
}